// round 2
// baseline (speedup 1.0000x reference)
#include <cuda_runtime.h>
#include <cstdint>

typedef unsigned long long ull;

#define D 128
#define MAXN 100000
#define BM 64
#define GEMM_THREADS 256
#define BN_EPS 1e-5f

// ---------------- scratch (device globals; no runtime allocation) -----------
__device__ __align__(16) float g_agg[(size_t)MAXN * D];   // aggregated messages
__device__ __align__(16) float g_y[(size_t)MAXN * D];     // pre-BN activations
__device__ float g_csrc[MAXN];
__device__ float g_cdst[MAXN];
__device__ int   g_odeg[MAXN];
__device__ int   g_ideg[MAXN];
__device__ __align__(16) float g_colsum[D];
__device__ __align__(16) float g_colsq[D];
__device__ __align__(16) float g_scale[D];
__device__ __align__(16) float g_shift[D];

// ---------------- degree histograms -----------------------------------------
__global__ void k_degrees(const int* __restrict__ src, const int* __restrict__ dst, int E) {
    int e = blockIdx.x * blockDim.x + threadIdx.x;
    if (e < E) {
        atomicAdd(&g_odeg[src[e]], 1);
        atomicAdd(&g_ideg[dst[e]], 1);
    }
}

__global__ void k_cnorm(int N) {
    int i = blockIdx.x * blockDim.x + threadIdx.x;
    if (i < N) {
        g_csrc[i] = rsqrtf(fmaxf((float)g_odeg[i], 1.0f));
        g_cdst[i] = rsqrtf(fmaxf((float)g_ideg[i], 1.0f));
    }
}

// ---------------- edge aggregation: warp per edge, v4 reduction --------------
__global__ __launch_bounds__(256) void k_aggregate(
    const float4* __restrict__ x4, const int* __restrict__ src,
    const int* __restrict__ dst, int E) {
    int t = blockIdx.x * blockDim.x + threadIdx.x;
    int e = t >> 5;
    if (e >= E) return;
    int lane = t & 31;
    int s = __ldg(&src[e]);
    int d = __ldg(&dst[e]);
    float c = g_csrc[s];
    float4 v = __ldg(&x4[(size_t)s * 32 + lane]);
    v.x *= c; v.y *= c; v.z *= c; v.w *= c;
    float* p = g_agg + ((size_t)d * D + lane * 4);
    asm volatile("red.global.add.v4.f32 [%0], {%1, %2, %3, %4};"
                 :: "l"(p), "f"(v.x), "f"(v.y), "f"(v.z), "f"(v.w) : "memory");
}

// ---------------- fused dual GEMM via fma.rn.f32x2 ---------------------------
// pair lanes = (h-branch, res-branch):
//   A tile: As2[m][k] = {agg[m][k]*c_dst[m], x[m][k]}   (BM x 128 float2)
//   W tile: Ws2[k][n] = {W[k][n], Wr[k][n]}             (128 x 128 float2)
//   acc = {h, res}; epilogue: y = relu(h+b) + relu(res+br), plus BN col sums.
__global__ __launch_bounds__(GEMM_THREADS, 1) void k_gemm_fused(
    const float4* __restrict__ x4, const float* __restrict__ W,
    const float* __restrict__ b, const float* __restrict__ Wr,
    const float* __restrict__ br, int N, int numTiles) {
    extern __shared__ float smem[];
    float* ws_f = smem;                 // D*D*2 floats = 128 KB
    float* as_f = smem + D * D * 2;     // BM*D*2 floats = 64 KB
    const ull* Ws2u = (const ull*)ws_f;
    const ull* As2u = (const ull*)as_f;
    const float4* agg4 = (const float4*)g_agg;

    int tid = threadIdx.x;
    int tx = tid & 31, ty = tid >> 5;
    int m0 = ty * 8;

    // load interleaved weights once per block (persistent blocks)
    {
        const float4* W4  = (const float4*)W;
        const float4* Wr4 = (const float4*)Wr;
        float4* Wd = (float4*)ws_f;
        for (int i = tid; i < D * D / 4; i += GEMM_THREADS) {
            float4 w  = __ldg(&W4[i]);
            float4 wr = __ldg(&Wr4[i]);
            Wd[2 * i]     = make_float4(w.x, wr.x, w.y, wr.y);
            Wd[2 * i + 1] = make_float4(w.z, wr.z, w.w, wr.w);
        }
    }
    float bn[4], brn[4];
#pragma unroll
    for (int c = 0; c < 4; c++) { bn[c] = __ldg(&b[tx + 32 * c]); brn[c] = __ldg(&br[tx + 32 * c]); }

    float ts[4] = {0.f, 0.f, 0.f, 0.f};
    float tq[4] = {0.f, 0.f, 0.f, 0.f};

    for (int tile = blockIdx.x; tile < numTiles; tile += gridDim.x) {
        int row0 = tile * BM;
        __syncthreads();   // previous tile's smem reads done before overwrite
        float4* Ad = (float4*)as_f;
        for (int i = tid; i < BM * (D / 4); i += GEMM_THREADS) {
            int r = i >> 5, kq = i & 31;
            int row = row0 + r;
            float4 va = make_float4(0.f, 0.f, 0.f, 0.f);
            float4 vx = va;
            float cd = 0.f;
            if (row < N) {
                va = __ldg(&agg4[(size_t)row * 32 + kq]);
                vx = __ldg(&x4[(size_t)row * 32 + kq]);
                cd = g_cdst[row];
            }
            Ad[r * 64 + 2 * kq]     = make_float4(va.x * cd, vx.x, va.y * cd, vx.y);
            Ad[r * 64 + 2 * kq + 1] = make_float4(va.z * cd, vx.z, va.w * cd, vx.w);
        }
        __syncthreads();

        ull acc[8][4];
#pragma unroll
        for (int i = 0; i < 8; i++)
#pragma unroll
            for (int c = 0; c < 4; c++) acc[i][c] = 0ull;

#pragma unroll 4
        for (int k = 0; k < D; k++) {
            ull a[8];
#pragma unroll
            for (int i = 0; i < 8; i++) a[i] = As2u[(m0 + i) * D + k];    // broadcast
            ull w[4];
#pragma unroll
            for (int c = 0; c < 4; c++) w[c] = Ws2u[k * D + tx + 32 * c]; // conflict-free
#pragma unroll
            for (int i = 0; i < 8; i++)
#pragma unroll
                for (int c = 0; c < 4; c++)
                    asm("fma.rn.f32x2 %0, %1, %2, %0;" : "+l"(acc[i][c]) : "l"(a[i]), "l"(w[c]));
        }

#pragma unroll
        for (int i = 0; i < 8; i++) {
            int row = row0 + m0 + i;
            if (row < N) {
#pragma unroll
                for (int c = 0; c < 4; c++) {
                    float h  = __uint_as_float((unsigned)(acc[i][c] & 0xffffffffull));
                    float r2 = __uint_as_float((unsigned)(acc[i][c] >> 32));
                    float v = fmaxf(h + bn[c], 0.f) + fmaxf(r2 + brn[c], 0.f);
                    g_y[(size_t)row * D + tx + 32 * c] = v;
                    ts[c] += v;
                    tq[c] += v * v;
                }
            }
        }
    }
#pragma unroll
    for (int c = 0; c < 4; c++) {
        atomicAdd(&g_colsum[tx + 32 * c], ts[c]);
        atomicAdd(&g_colsq[tx + 32 * c], tq[c]);
    }
}

// ---------------- BN parameter fold + apply ----------------------------------
__global__ void k_bnparams(const float* __restrict__ gamma, const float* __restrict__ beta, float invN) {
    int j = threadIdx.x;
    float mean = g_colsum[j] * invN;
    float var = fmaxf(g_colsq[j] * invN - mean * mean, 0.f);
    float s = rsqrtf(var + BN_EPS) * __ldg(&gamma[j]);
    g_scale[j] = s;
    g_shift[j] = __ldg(&beta[j]) - mean * s;
}

__global__ __launch_bounds__(256) void k_bnapply(float4* __restrict__ out4, int total4) {
    int i = blockIdx.x * blockDim.x + threadIdx.x;
    if (i >= total4) return;
    const float4* y4 = (const float4*)g_y;
    const float4* s4 = (const float4*)g_scale;
    const float4* t4 = (const float4*)g_shift;
    int c = i & 31;
    float4 v = y4[i];
    float4 s = s4[c];
    float4 t = t4[c];
    out4[i] = make_float4(v.x * s.x + t.x, v.y * s.y + t.y,
                          v.z * s.z + t.z, v.w * s.w + t.w);
}

// ---------------- launch ------------------------------------------------------
extern "C" void kernel_launch(void* const* d_in, const int* in_sizes, int n_in,
                              void* d_out, int out_size) {
    const float* x     = (const float*)d_in[0];
    const float* W     = (const float*)d_in[1];
    const float* b     = (const float*)d_in[2];
    const float* Wr    = (const float*)d_in[3];
    const float* br    = (const float*)d_in[4];
    const float* gamma = (const float*)d_in[5];
    const float* beta  = (const float*)d_in[6];
    const int*   src   = (const int*)d_in[7];
    const int*   dst   = (const int*)d_in[8];

    const int N = in_sizes[0] / D;
    const int E = in_sizes[7];

    // scratch pointers
    void *p_agg, *p_odeg, *p_ideg, *p_colsum, *p_colsq;
    cudaGetSymbolAddress(&p_agg, g_agg);
    cudaGetSymbolAddress(&p_odeg, g_odeg);
    cudaGetSymbolAddress(&p_ideg, g_ideg);
    cudaGetSymbolAddress(&p_colsum, g_colsum);
    cudaGetSymbolAddress(&p_colsq, g_colsq);

    cudaMemsetAsync(p_agg, 0, (size_t)N * D * sizeof(float));
    cudaMemsetAsync(p_odeg, 0, (size_t)N * sizeof(int));
    cudaMemsetAsync(p_ideg, 0, (size_t)N * sizeof(int));
    cudaMemsetAsync(p_colsum, 0, D * sizeof(float));
    cudaMemsetAsync(p_colsq, 0, D * sizeof(float));

    // degrees + norm coefficients
    k_degrees<<<(E + 255) / 256, 256>>>(src, dst, E);
    k_cnorm<<<(N + 255) / 256, 256>>>(N);

    // edge aggregation (warp per edge)
    {
        long long threads = (long long)E * 32;
        int blocks = (int)((threads + 255) / 256);
        k_aggregate<<<blocks, 256>>>((const float4*)x, src, dst, E);
    }

    // fused dual GEMM + epilogue + BN partial sums
    {
        const int smemBytes = (D * D * 2 + BM * D * 2) * (int)sizeof(float); // 192 KB
        cudaFuncSetAttribute(k_gemm_fused, cudaFuncAttributeMaxDynamicSharedMemorySize, smemBytes);
        int numTiles = (N + BM - 1) / BM;
        int grid = numTiles < 152 ? numTiles : 152;
        k_gemm_fused<<<grid, GEMM_THREADS, smemBytes>>>(
            (const float4*)x, W, b, Wr, br, N, numTiles);
    }

    // BN params + apply
    k_bnparams<<<1, D>>>(gamma, beta, 1.0f / (float)N);
    {
        int total4 = N * (D / 4);
        k_bnapply<<<(total4 + 255) / 256, 256>>>((float4*)d_out, total4);
    }
}

// round 3
// speedup vs baseline: 1.4475x; 1.4475x over previous
#include <cuda_runtime.h>
#include <cstdint>

typedef unsigned long long ull;

#define D 128
#define MAXN 100000
#define BM 64
#define BN_EPS 1e-5f

// ---------------- scratch (device globals; no runtime allocation) -----------
__device__ __align__(16) float g_agg[(size_t)MAXN * D];
__device__ __align__(16) float g_y[(size_t)MAXN * D];
__device__ float g_csrc[MAXN];
__device__ float g_cdst[MAXN];
__device__ int   g_odeg[MAXN];
__device__ int   g_ideg[MAXN];
__device__ __align__(16) float g_colsum[D];
__device__ __align__(16) float g_colsq[D];
__device__ __align__(16) float g_scale[D];
__device__ __align__(16) float g_shift[D];

// ---------------- degree histograms -----------------------------------------
__global__ void k_degrees(const int* __restrict__ src, const int* __restrict__ dst, int E) {
    int e = blockIdx.x * blockDim.x + threadIdx.x;
    if (e < E) {
        atomicAdd(&g_odeg[src[e]], 1);
        atomicAdd(&g_ideg[dst[e]], 1);
    }
}

__global__ void k_cnorm(int N) {
    int i = blockIdx.x * blockDim.x + threadIdx.x;
    if (i < N) {
        g_csrc[i] = rsqrtf(fmaxf((float)g_odeg[i], 1.0f));
        g_cdst[i] = rsqrtf(fmaxf((float)g_ideg[i], 1.0f));
    }
}

// ---------------- edge aggregation: warp per edge, v4 reduction --------------
__global__ __launch_bounds__(256) void k_aggregate(
    const float4* __restrict__ x4, const int* __restrict__ src,
    const int* __restrict__ dst, int E) {
    int t = blockIdx.x * blockDim.x + threadIdx.x;
    int e = t >> 5;
    if (e >= E) return;
    int lane = t & 31;
    int s = __ldg(&src[e]);
    int d = __ldg(&dst[e]);
    float c = g_csrc[s];
    float4 v = __ldg(&x4[(size_t)s * 32 + lane]);
    v.x *= c; v.y *= c; v.z *= c; v.w *= c;
    float* p = g_agg + ((size_t)d * D + lane * 4);
    asm volatile("red.global.add.v4.f32 [%0], {%1, %2, %3, %4};"
                 :: "l"(p), "f"(v.x), "f"(v.y), "f"(v.z), "f"(v.w) : "memory");
}

// ---------------- tf32 tensor-core fused dual GEMM ---------------------------
__device__ __forceinline__ unsigned f2tf(float f) {
    unsigned u; asm("cvt.rna.tf32.f32 %0, %1;" : "=r"(u) : "f"(f)); return u;
}

#define MMA_TF32(d, a, b0_, b1_) \
    asm volatile("mma.sync.aligned.m16n8k8.row.col.f32.tf32.tf32.f32 " \
        "{%0,%1,%2,%3},{%4,%5,%6,%7},{%8,%9},{%0,%1,%2,%3};" \
        : "+f"(d[0]), "+f"(d[1]), "+f"(d[2]), "+f"(d[3]) \
        : "r"(a[0]), "r"(a[1]), "r"(a[2]), "r"(a[3]), "r"(b0_), "r"(b1_))

// Block: 256 thr = 8 warps = 4 (m) x 2 (n). Warp tile 16 rows x 64 cols, both
// branches. Per block row-tile BM=64 x 128 cols.
// smem: ws = fragment-major tf32 W/Wr (128KB, built once),
//       as = row-xor-swizzled tf32 A tile, both branches (64KB).
__global__ __launch_bounds__(256, 1) void k_gemm_tf32(
    const float* __restrict__ W, const float* __restrict__ bb,
    const float* __restrict__ Wr, const float* __restrict__ brr,
    int N, int numTiles)
{
    extern __shared__ unsigned smem_u[];
    unsigned* ws = smem_u;            // 32768 words = 128KB
    unsigned* as = smem_u + 32768;    // 16384 words = 64KB

    const int tid  = threadIdx.x;
    const int lane = tid & 31;
    const int wid  = tid >> 5;
    const int mw   = wid >> 1;     // 0..3
    const int nw   = wid & 1;      // 0..1
    const int tig  = lane & 3;     // thread-in-group
    const int gid  = lane >> 2;    // group id 0..7

    const float4* agg4 = (const float4*)g_agg;
    const float4* x4g  = (const float4*)((const float*)0); // placeholder replaced below
    // x passed via g pointer trick not needed: use param-free access? -> pass x:
    // (x is bound through kernel arg below)
    (void)x4g;

    // ---- one-time: build fragment-major packed W (tf32) ----
    // layout: region(nw,br,t) of 1024 words; within: lane*32 + ((j2 ^ (lane&7))<<2)
    // uint4 = {b0(j=2*j2), b1(j=2*j2), b0(j=2*j2+1), b1(j=2*j2+1)}
    for (int cell = tid; cell < 8192; cell += 256) {
        int j2  = cell & 7;
        int l   = (cell >> 3) & 31;
        int t   = (cell >> 8) & 7;
        int cbr = (cell >> 11) & 1;
        int cnw = (cell >> 12) & 1;
        const float* Wb = cbr ? Wr : W;
        int n  = cnw * 64 + t * 8 + (l >> 2);
        int k0 = j2 * 16 + (l & 3);
        uint4 v;
        v.x = f2tf(__ldg(&Wb[(k0     ) * D + n]));
        v.y = f2tf(__ldg(&Wb[(k0 +  4) * D + n]));
        v.z = f2tf(__ldg(&Wb[(k0 +  8) * D + n]));
        v.w = f2tf(__ldg(&Wb[(k0 + 12) * D + n]));
        int region = (cnw * 2 + cbr) * 8 + t;
        *(uint4*)(ws + region * 1024 + l * 32 + ((j2 ^ (l & 7)) << 2)) = v;
    }

    float ts[16], tq[16];
#pragma unroll
    for (int i = 0; i < 16; i++) { ts[i] = 0.f; tq[i] = 0.f; }

    __syncthreads();  // ws ready
    // (placed before loop; per-tile syncs below protect as)
}

// The real GEMM kernel (with x as an argument) — the above was refactored in:
__global__ __launch_bounds__(256, 1) void k_gemm_tf32_main(
    const float4* __restrict__ x4, const float* __restrict__ W,
    const float* __restrict__ bb, const float* __restrict__ Wr,
    const float* __restrict__ brr, int N, int numTiles)
{
    extern __shared__ unsigned smem_u[];
    unsigned* ws = smem_u;            // 32768 words = 128KB
    unsigned* as = smem_u + 32768;    // 16384 words = 64KB

    const int tid  = threadIdx.x;
    const int lane = tid & 31;
    const int wid  = tid >> 5;
    const int mw   = wid >> 1;     // 0..3
    const int nw   = wid & 1;      // 0..1
    const int tig  = lane & 3;
    const int gid  = lane >> 2;

    const float4* agg4 = (const float4*)g_agg;

    // ---- one-time: fragment-major packed W/Wr in tf32 ----
    for (int cell = tid; cell < 8192; cell += 256) {
        int j2  = cell & 7;
        int l   = (cell >> 3) & 31;
        int t   = (cell >> 8) & 7;
        int cbr = (cell >> 11) & 1;
        int cnw = (cell >> 12) & 1;
        const float* Wb = cbr ? Wr : W;
        int n  = cnw * 64 + t * 8 + (l >> 2);
        int k0 = j2 * 16 + (l & 3);
        uint4 v;
        v.x = f2tf(__ldg(&Wb[(k0     ) * D + n]));
        v.y = f2tf(__ldg(&Wb[(k0 +  4) * D + n]));
        v.z = f2tf(__ldg(&Wb[(k0 +  8) * D + n]));
        v.w = f2tf(__ldg(&Wb[(k0 + 12) * D + n]));
        int region = (cnw * 2 + cbr) * 8 + t;
        *(uint4*)(ws + region * 1024 + l * 32 + ((j2 ^ (l & 7)) << 2)) = v;
    }

    float ts[16], tq[16];
#pragma unroll
    for (int i = 0; i < 16; i++) { ts[i] = 0.f; tq[i] = 0.f; }

    // ---- prefetch first tile into registers (scaled by c_dst for branch 0) --
    float4 pf[16];
    int tile = blockIdx.x;
    {
        int row0 = tile * BM;
#pragma unroll
        for (int i = 0; i < 16; i++) {
            int idx = tid + i * 256;
            int kq  = idx & 31;
            int row = (idx >> 5) & 63;
            int cbr = (idx >> 11) & 1;
            int grow = row0 + row;
            float4 v = make_float4(0.f, 0.f, 0.f, 0.f);
            if (grow < N) {
                if (cbr == 0) {
                    v = __ldg(&agg4[(size_t)grow * 32 + kq]);
                    float cd = __ldg(&g_cdst[grow]);
                    v.x *= cd; v.y *= cd; v.z *= cd; v.w *= cd;
                } else {
                    v = __ldg(&x4[(size_t)grow * 32 + kq]);
                }
            }
            pf[i] = v;
        }
    }

    __syncthreads();  // ws ready before first mma use

    for (; tile < numTiles; tile += gridDim.x) {
        int row0 = tile * BM;

        // store prefetched tile to swizzled tf32 smem
#pragma unroll
        for (int i = 0; i < 16; i++) {
            int idx = tid + i * 256;
            int kq  = idx & 31;
            int row = (idx >> 5) & 63;
            int cbr = (idx >> 11) & 1;
            uint4 u;
            u.x = f2tf(pf[i].x); u.y = f2tf(pf[i].y);
            u.z = f2tf(pf[i].z); u.w = f2tf(pf[i].w);
            *(uint4*)(as + (cbr * 64 + row) * 128 + ((kq * 4) ^ ((row & 7) * 4))) = u;
        }
        __syncthreads();

        // prefetch NEXT tile while MMAs run
        int ntile = tile + gridDim.x;
        if (ntile < numTiles) {
            int nrow0 = ntile * BM;
#pragma unroll
            for (int i = 0; i < 16; i++) {
                int idx = tid + i * 256;
                int kq  = idx & 31;
                int row = (idx >> 5) & 63;
                int cbr = (idx >> 11) & 1;
                int grow = nrow0 + row;
                float4 v = make_float4(0.f, 0.f, 0.f, 0.f);
                if (grow < N) {
                    if (cbr == 0) {
                        v = __ldg(&agg4[(size_t)grow * 32 + kq]);
                        float cd = __ldg(&g_cdst[grow]);
                        v.x *= cd; v.y *= cd; v.z *= cd; v.w *= cd;
                    } else {
                        v = __ldg(&x4[(size_t)grow * 32 + kq]);
                    }
                }
                pf[i] = v;
            }
        }

        // ---- MMA mainloop: acc[t][br][4] ----
        float acc[8][2][4];
#pragma unroll
        for (int t = 0; t < 8; t++)
#pragma unroll
            for (int cbr = 0; cbr < 2; cbr++)
#pragma unroll
                for (int r = 0; r < 4; r++) acc[t][cbr][r] = 0.f;

        const int r0 = mw * 16 + gid;          // fragment row (local)
        const int swz = gid * 4;               // xor swizzle for this row group

#pragma unroll
        for (int jp = 0; jp < 8; jp++) {       // kstep pairs (k = 16*jp .. +15)
#pragma unroll
            for (int cbr = 0; cbr < 2; cbr++) {
                unsigned a[2][4];
#pragma unroll
                for (int dj = 0; dj < 2; dj++) {
                    int k0 = (jp * 2 + dj) * 8 + tig;
                    const unsigned* base = as + (cbr * 64 + r0) * 128;
                    a[dj][0] = base[(k0    ) ^ swz];
                    a[dj][1] = base[1024 + ((k0    ) ^ swz)];   // row+8: +8*128 words
                    a[dj][2] = base[(k0 + 4) ^ swz];
                    a[dj][3] = base[1024 + ((k0 + 4) ^ swz)];
                }
#pragma unroll
                for (int t = 0; t < 8; t++) {
                    int region = (nw * 2 + cbr) * 8 + t;
                    uint4 bf = *(const uint4*)(ws + region * 1024 + lane * 32 +
                                               ((jp ^ (lane & 7)) << 2));
                    MMA_TF32(acc[t][cbr], a[0], bf.x, bf.y);
                    MMA_TF32(acc[t][cbr], a[1], bf.z, bf.w);
                }
            }
        }

        // ---- epilogue: relu+relu+add, write y, BN partial sums ----
        int rA = row0 + mw * 16 + gid;
        int rB = rA + 8;
#pragma unroll
        for (int t = 0; t < 8; t++) {
            int col = nw * 64 + t * 8 + 2 * tig;
            float b0 = __ldg(&bb[col]),  b1 = __ldg(&bb[col + 1]);
            float q0 = __ldg(&brr[col]), q1 = __ldg(&brr[col + 1]);
            if (rA < N) {
                float v0 = fmaxf(acc[t][0][0] + b0, 0.f) + fmaxf(acc[t][1][0] + q0, 0.f);
                float v1 = fmaxf(acc[t][0][1] + b1, 0.f) + fmaxf(acc[t][1][1] + q1, 0.f);
                *(float2*)&g_y[(size_t)rA * D + col] = make_float2(v0, v1);
                ts[2 * t] += v0; tq[2 * t] += v0 * v0;
                ts[2 * t + 1] += v1; tq[2 * t + 1] += v1 * v1;
            }
            if (rB < N) {
                float v2 = fmaxf(acc[t][0][2] + b0, 0.f) + fmaxf(acc[t][1][2] + q0, 0.f);
                float v3 = fmaxf(acc[t][0][3] + b1, 0.f) + fmaxf(acc[t][1][3] + q1, 0.f);
                *(float2*)&g_y[(size_t)rB * D + col] = make_float2(v2, v3);
                ts[2 * t] += v2; tq[2 * t] += v2 * v2;
                ts[2 * t + 1] += v3; tq[2 * t + 1] += v3 * v3;
            }
        }
        __syncthreads();  // all mma reads of `as` done before next store phase
    }

    // ---- BN sums: reduce across the 8 lanes sharing each column set ----
#pragma unroll
    for (int i = 0; i < 16; i++) {
#pragma unroll
        for (int m = 4; m <= 16; m <<= 1) {
            ts[i] += __shfl_xor_sync(0xffffffffu, ts[i], m);
            tq[i] += __shfl_xor_sync(0xffffffffu, tq[i], m);
        }
    }
    if (gid == 0) {
#pragma unroll
        for (int i = 0; i < 16; i++) {
            int col = nw * 64 + (i >> 1) * 8 + 2 * tig + (i & 1);
            atomicAdd(&g_colsum[col], ts[i]);
            atomicAdd(&g_colsq[col], tq[i]);
        }
    }
}

// ---------------- BN parameter fold + apply ----------------------------------
__global__ void k_bnparams(const float* __restrict__ gamma, const float* __restrict__ beta, float invN) {
    int j = threadIdx.x;
    float mean = g_colsum[j] * invN;
    float var = fmaxf(g_colsq[j] * invN - mean * mean, 0.f);
    float s = rsqrtf(var + BN_EPS) * __ldg(&gamma[j]);
    g_scale[j] = s;
    g_shift[j] = __ldg(&beta[j]) - mean * s;
}

__global__ __launch_bounds__(256) void k_bnapply(float4* __restrict__ out4, int total4) {
    int i = blockIdx.x * blockDim.x + threadIdx.x;
    if (i >= total4) return;
    const float4* y4 = (const float4*)g_y;
    const float4* s4 = (const float4*)g_scale;
    const float4* t4 = (const float4*)g_shift;
    int c = i & 31;
    float4 v = y4[i];
    float4 s = s4[c];
    float4 t = t4[c];
    out4[i] = make_float4(v.x * s.x + t.x, v.y * s.y + t.y,
                          v.z * s.z + t.z, v.w * s.w + t.w);
}

// ---------------- launch ------------------------------------------------------
extern "C" void kernel_launch(void* const* d_in, const int* in_sizes, int n_in,
                              void* d_out, int out_size) {
    const float* x     = (const float*)d_in[0];
    const float* W     = (const float*)d_in[1];
    const float* b     = (const float*)d_in[2];
    const float* Wr    = (const float*)d_in[3];
    const float* br    = (const float*)d_in[4];
    const float* gamma = (const float*)d_in[5];
    const float* beta  = (const float*)d_in[6];
    const int*   src   = (const int*)d_in[7];
    const int*   dst   = (const int*)d_in[8];

    const int N = in_sizes[0] / D;
    const int E = in_sizes[7];

    void *p_agg, *p_odeg, *p_ideg, *p_colsum, *p_colsq;
    cudaGetSymbolAddress(&p_agg, g_agg);
    cudaGetSymbolAddress(&p_odeg, g_odeg);
    cudaGetSymbolAddress(&p_ideg, g_ideg);
    cudaGetSymbolAddress(&p_colsum, g_colsum);
    cudaGetSymbolAddress(&p_colsq, g_colsq);

    cudaMemsetAsync(p_agg, 0, (size_t)N * D * sizeof(float));
    cudaMemsetAsync(p_odeg, 0, (size_t)N * sizeof(int));
    cudaMemsetAsync(p_ideg, 0, (size_t)N * sizeof(int));
    cudaMemsetAsync(p_colsum, 0, D * sizeof(float));
    cudaMemsetAsync(p_colsq, 0, D * sizeof(float));

    k_degrees<<<(E + 255) / 256, 256>>>(src, dst, E);
    k_cnorm<<<(N + 255) / 256, 256>>>(N);

    {
        long long threads = (long long)E * 32;
        int blocks = (int)((threads + 255) / 256);
        k_aggregate<<<blocks, 256>>>((const float4*)x, src, dst, E);
    }

    {
        const int smemBytes = (32768 + 16384) * (int)sizeof(unsigned); // 192 KB
        cudaFuncSetAttribute(k_gemm_tf32_main, cudaFuncAttributeMaxDynamicSharedMemorySize, smemBytes);
        int numTiles = (N + BM - 1) / BM;
        int grid = numTiles < 152 ? numTiles : 152;
        k_gemm_tf32_main<<<grid, 256, smemBytes>>>(
            (const float4*)x, W, b, Wr, br, N, numTiles);
    }

    k_bnparams<<<1, D>>>(gamma, beta, 1.0f / (float)N);
    {
        int total4 = N * (D / 4);
        k_bnapply<<<(total4 + 255) / 256, 256>>>((float4*)d_out, total4);
    }
}

// round 4
// speedup vs baseline: 1.6223x; 1.1208x over previous
#include <cuda_runtime.h>
#include <cstdint>

#define D 128
#define MAXN 100000
#define BM 64
#define BN_EPS 1e-5f

// ---------------- scratch (device globals; no runtime allocation) -----------
__device__ __align__(16) float g_agg[(size_t)MAXN * D];
__device__ __align__(16) float g_y[(size_t)MAXN * D];
__device__ float g_csrc[MAXN];
__device__ float g_cdst[MAXN];
__device__ int   g_odeg[MAXN];
__device__ int   g_ideg[MAXN];
__device__ __align__(16) float g_colsum[D];
__device__ __align__(16) float g_colsq[D];
__device__ __align__(16) float g_scale[D];
__device__ __align__(16) float g_shift[D];

// ---------------- degree histograms -----------------------------------------
__global__ void k_degrees(const int* __restrict__ src, const int* __restrict__ dst, int E) {
    int e = blockIdx.x * blockDim.x + threadIdx.x;
    if (e < E) {
        atomicAdd(&g_odeg[src[e]], 1);
        atomicAdd(&g_ideg[dst[e]], 1);
    }
}

__global__ void k_cnorm(int N) {
    int i = blockIdx.x * blockDim.x + threadIdx.x;
    if (i < N) {
        g_csrc[i] = rsqrtf(fmaxf((float)g_odeg[i], 1.0f));
        g_cdst[i] = rsqrtf(fmaxf((float)g_ideg[i], 1.0f));
    }
}

// ---------------- edge aggregation: warp per edge, v4 reduction --------------
__global__ __launch_bounds__(256) void k_aggregate(
    const float4* __restrict__ x4, const int* __restrict__ src,
    const int* __restrict__ dst, int E) {
    int t = blockIdx.x * blockDim.x + threadIdx.x;
    int e = t >> 5;
    if (e >= E) return;
    int lane = t & 31;
    int s = __ldg(&src[e]);
    int d = __ldg(&dst[e]);
    float c = g_csrc[s];
    float4 v = __ldg(&x4[(size_t)s * 32 + lane]);
    v.x *= c; v.y *= c; v.z *= c; v.w *= c;
    float* p = g_agg + ((size_t)d * D + lane * 4);
    asm volatile("red.global.add.v4.f32 [%0], {%1, %2, %3, %4};"
                 :: "l"(p), "f"(v.x), "f"(v.y), "f"(v.z), "f"(v.w) : "memory");
}

// ---------------- tf32 tensor-core fused dual GEMM ---------------------------
__device__ __forceinline__ unsigned f2tf(float f) {
    unsigned u; asm("cvt.rna.tf32.f32 %0, %1;" : "=r"(u) : "f"(f)); return u;
}
__device__ __forceinline__ unsigned r2tf(unsigned x) {
    unsigned u; asm("cvt.rna.tf32.f32 %0, %1;" : "=r"(u) : "f"(__uint_as_float(x))); return u;
}

#define MMA_TF32(d, a, b0_, b1_) \
    asm volatile("mma.sync.aligned.m16n8k8.row.col.f32.tf32.tf32.f32 " \
        "{%0,%1,%2,%3},{%4,%5,%6,%7},{%8,%9},{%0,%1,%2,%3};" \
        : "+f"(d[0]), "+f"(d[1]), "+f"(d[2]), "+f"(d[3]) \
        : "r"(a[0]), "r"(a[1]), "r"(a[2]), "r"(a[3]), "r"(b0_), "r"(b1_))

// issue one (tile,branch) stage: raw fp32 rows -> swizzled smem via cp.async
__device__ __forceinline__ void stage_load(unsigned* buf, const float4* __restrict__ srcb,
                                           int row0, int N, int tid) {
#pragma unroll
    for (int i = 0; i < 8; i++) {
        int idx = tid + i * 256;
        int row = idx >> 5, kq = idx & 31;
        int grow = row0 + row;
        unsigned daddr = (unsigned)__cvta_generic_to_shared(
            buf + row * 128 + ((kq * 4) ^ ((row & 7) * 4)));
        const float4* s = srcb + (size_t)(grow < N ? grow : 0) * 32 + kq;
        int sz = grow < N ? 16 : 0;
        asm volatile("cp.async.cg.shared.global [%0], [%1], 16, %2;"
                     :: "r"(daddr), "l"(s), "r"(sz));
    }
}

// jp-loop for one branch; ACC is acc0 or acc1 (compile-time array)
#define MMA_STAGE(ACC, BR)                                                         \
    _Pragma("unroll")                                                              \
    for (int jp = 0; jp < 8; jp++) {                                               \
        unsigned a[2][2][4];                                                       \
        _Pragma("unroll")                                                          \
        for (int mf = 0; mf < 2; mf++) {                                           \
            const unsigned* base = asb + (mw * 32 + mf * 16 + gid) * 128;          \
            _Pragma("unroll")                                                      \
            for (int dj = 0; dj < 2; dj++) {                                       \
                int k0 = jp * 16 + dj * 8 + tig;                                   \
                a[mf][dj][0] = r2tf(base[(k0) ^ swz]);                             \
                a[mf][dj][1] = r2tf(base[1024 + ((k0) ^ swz)]);                    \
                a[mf][dj][2] = r2tf(base[(k0 + 4) ^ swz]);                         \
                a[mf][dj][3] = r2tf(base[1024 + ((k0 + 4) ^ swz)]);                \
            }                                                                      \
        }                                                                          \
        _Pragma("unroll")                                                          \
        for (int t = 0; t < 4; t++) {                                              \
            int region = (nw * 2 + (BR)) * 4 + t;                                  \
            uint4 bf = *(const uint4*)(ws + region * 1024 + lane * 32 +            \
                                       ((jp ^ (lane & 7)) << 2));                  \
            _Pragma("unroll")                                                      \
            for (int mf = 0; mf < 2; mf++) {                                       \
                MMA_TF32(ACC[mf][t], a[mf][0], bf.x, bf.y);                        \
                MMA_TF32(ACC[mf][t], a[mf][1], bf.z, bf.w);                        \
            }                                                                      \
        }                                                                          \
    }

// Block: 256 thr = 8 warps = 2(m) x 4(n); warp tile m32 x n32, both branches.
// smem: ws = fragment-major tf32 W/Wr (128KB), as0/as1 = 32KB A stages.
__global__ __launch_bounds__(256, 1) void k_gemm_tf32(
    const float4* __restrict__ x4, const float* __restrict__ W,
    const float* __restrict__ bb, const float* __restrict__ Wr,
    const float* __restrict__ brr, int N, int numTiles)
{
    extern __shared__ unsigned smem_u[];
    unsigned* ws  = smem_u;           // 32768 words = 128KB
    unsigned* as0 = smem_u + 32768;   //  8192 words =  32KB
    unsigned* as1 = smem_u + 40960;   //  8192 words =  32KB

    const int tid  = threadIdx.x;
    const int lane = tid & 31;
    const int wid  = tid >> 5;
    const int mw   = wid >> 2;     // 0..1
    const int nw   = wid & 3;      // 0..3
    const int tig  = lane & 3;
    const int gid  = lane >> 2;
    const int swz  = gid * 4;

    const float4* agg4 = (const float4*)g_agg;

    // ---- one-time: fragment-major packed W/Wr in tf32 (rounded) ----
    for (int cell = tid; cell < 8192; cell += 256) {
        int j2  = cell & 7;
        int l   = (cell >> 3) & 31;
        int t   = (cell >> 8) & 3;
        int cbr = (cell >> 10) & 1;
        int cnw = (cell >> 11) & 3;
        const float* Wb = cbr ? Wr : W;
        int n  = cnw * 32 + t * 8 + (l >> 2);
        int k0 = j2 * 16 + (l & 3);
        uint4 v;
        v.x = f2tf(__ldg(&Wb[(k0     ) * D + n]));
        v.y = f2tf(__ldg(&Wb[(k0 +  4) * D + n]));
        v.z = f2tf(__ldg(&Wb[(k0 +  8) * D + n]));
        v.w = f2tf(__ldg(&Wb[(k0 + 12) * D + n]));
        int region = (cnw * 2 + cbr) * 4 + t;
        *(uint4*)(ws + region * 1024 + l * 32 + ((j2 ^ (l & 7)) << 2)) = v;
    }

    // biases for this thread's 8 output columns
    float b_[8], q_[8];
#pragma unroll
    for (int t = 0; t < 4; t++) {
        int col = nw * 32 + t * 8 + 2 * tig;
        b_[2 * t] = __ldg(&bb[col]);   b_[2 * t + 1] = __ldg(&bb[col + 1]);
        q_[2 * t] = __ldg(&brr[col]);  q_[2 * t + 1] = __ldg(&brr[col + 1]);
    }

    float ts[8], tq[8];
#pragma unroll
    for (int i = 0; i < 8; i++) { ts[i] = 0.f; tq[i] = 0.f; }

    const int nT = (numTiles - blockIdx.x + gridDim.x - 1) / gridDim.x;
    const int totalS = nT * 2;

    // prologue: stages 0 (agg of tile0) and 1 (x of tile0)
    stage_load(as0, agg4, blockIdx.x * BM, N, tid);
    asm volatile("cp.async.commit_group;");
    stage_load(as1, x4, blockIdx.x * BM, N, tid);
    asm volatile("cp.async.commit_group;");

    float acc0[2][4][4], acc1[2][4][4];

    for (int s = 0; s < totalS; s++) {
        const int br   = s & 1;
        const int tile = blockIdx.x + (s >> 1) * gridDim.x;
        const int row0 = tile * BM;

        asm volatile("cp.async.wait_group 1;");
        __syncthreads();
        const unsigned* asb = br ? as1 : as0;

        if (br == 0) {
#pragma unroll
            for (int mf = 0; mf < 2; mf++)
#pragma unroll
                for (int t = 0; t < 4; t++)
#pragma unroll
                    for (int r = 0; r < 4; r++) { acc0[mf][t][r] = 0.f; acc1[mf][t][r] = 0.f; }
            MMA_STAGE(acc0, 0)
        } else {
            MMA_STAGE(acc1, 1)
        }

        __syncthreads();  // all reads of asb done before overwrite

        int s2 = s + 2;
        if (s2 < totalS) {
            int t2 = blockIdx.x + (s2 >> 1) * gridDim.x;
            stage_load((s2 & 1) ? as1 : as0, (s2 & 1) ? x4 : agg4, t2 * BM, N, tid);
        }
        asm volatile("cp.async.commit_group;");

        if (br == 1) {
            // epilogue: h*c_dst + b -> relu, + relu(res+br), write y, BN sums
#pragma unroll
            for (int mf = 0; mf < 2; mf++) {
                int rA = row0 + mw * 32 + mf * 16 + gid;
                int rB = rA + 8;
                float cdA = (rA < N) ? __ldg(&g_cdst[rA]) : 0.f;
                float cdB = (rB < N) ? __ldg(&g_cdst[rB]) : 0.f;
#pragma unroll
                for (int t = 0; t < 4; t++) {
                    int col = nw * 32 + t * 8 + 2 * tig;
                    if (rA < N) {
                        float v0 = fmaxf(acc0[mf][t][0] * cdA + b_[2 * t], 0.f)
                                 + fmaxf(acc1[mf][t][0] + q_[2 * t], 0.f);
                        float v1 = fmaxf(acc0[mf][t][1] * cdA + b_[2 * t + 1], 0.f)
                                 + fmaxf(acc1[mf][t][1] + q_[2 * t + 1], 0.f);
                        *(float2*)&g_y[(size_t)rA * D + col] = make_float2(v0, v1);
                        ts[2 * t] += v0; tq[2 * t] += v0 * v0;
                        ts[2 * t + 1] += v1; tq[2 * t + 1] += v1 * v1;
                    }
                    if (rB < N) {
                        float v2 = fmaxf(acc0[mf][t][2] * cdB + b_[2 * t], 0.f)
                                 + fmaxf(acc1[mf][t][2] + q_[2 * t], 0.f);
                        float v3 = fmaxf(acc0[mf][t][3] * cdB + b_[2 * t + 1], 0.f)
                                 + fmaxf(acc1[mf][t][3] + q_[2 * t + 1], 0.f);
                        *(float2*)&g_y[(size_t)rB * D + col] = make_float2(v2, v3);
                        ts[2 * t] += v2; tq[2 * t] += v2 * v2;
                        ts[2 * t + 1] += v3; tq[2 * t + 1] += v3 * v3;
                    }
                }
            }
        }
    }

    // ---- BN sums: lanes gid 0..7 hold identical column sets -> reduce ----
#pragma unroll
    for (int i = 0; i < 8; i++) {
#pragma unroll
        for (int m = 4; m <= 16; m <<= 1) {
            ts[i] += __shfl_xor_sync(0xffffffffu, ts[i], m);
            tq[i] += __shfl_xor_sync(0xffffffffu, tq[i], m);
        }
    }
    if (gid == 0) {
#pragma unroll
        for (int i = 0; i < 8; i++) {
            int col = nw * 32 + (i >> 1) * 8 + 2 * tig + (i & 1);
            atomicAdd(&g_colsum[col], ts[i]);
            atomicAdd(&g_colsq[col], tq[i]);
        }
    }
}

// ---------------- BN parameter fold + apply ----------------------------------
__global__ void k_bnparams(const float* __restrict__ gamma, const float* __restrict__ beta, float invN) {
    int j = threadIdx.x;
    float mean = g_colsum[j] * invN;
    float var = fmaxf(g_colsq[j] * invN - mean * mean, 0.f);
    float s = rsqrtf(var + BN_EPS) * __ldg(&gamma[j]);
    g_scale[j] = s;
    g_shift[j] = __ldg(&beta[j]) - mean * s;
}

__global__ __launch_bounds__(256) void k_bnapply(float4* __restrict__ out4, int total4) {
    int i = blockIdx.x * blockDim.x + threadIdx.x;
    if (i >= total4) return;
    const float4* y4 = (const float4*)g_y;
    const float4* s4 = (const float4*)g_scale;
    const float4* t4 = (const float4*)g_shift;
    int c = i & 31;
    float4 v = y4[i];
    float4 s = s4[c];
    float4 t = t4[c];
    out4[i] = make_float4(v.x * s.x + t.x, v.y * s.y + t.y,
                          v.z * s.z + t.z, v.w * s.w + t.w);
}

// ---------------- launch ------------------------------------------------------
extern "C" void kernel_launch(void* const* d_in, const int* in_sizes, int n_in,
                              void* d_out, int out_size) {
    const float* x     = (const float*)d_in[0];
    const float* W     = (const float*)d_in[1];
    const float* b     = (const float*)d_in[2];
    const float* Wr    = (const float*)d_in[3];
    const float* br    = (const float*)d_in[4];
    const float* gamma = (const float*)d_in[5];
    const float* beta  = (const float*)d_in[6];
    const int*   src   = (const int*)d_in[7];
    const int*   dst   = (const int*)d_in[8];

    const int N = in_sizes[0] / D;
    const int E = in_sizes[7];

    void *p_agg, *p_odeg, *p_ideg, *p_colsum, *p_colsq;
    cudaGetSymbolAddress(&p_agg, g_agg);
    cudaGetSymbolAddress(&p_odeg, g_odeg);
    cudaGetSymbolAddress(&p_ideg, g_ideg);
    cudaGetSymbolAddress(&p_colsum, g_colsum);
    cudaGetSymbolAddress(&p_colsq, g_colsq);

    cudaMemsetAsync(p_agg, 0, (size_t)N * D * sizeof(float));
    cudaMemsetAsync(p_odeg, 0, (size_t)N * sizeof(int));
    cudaMemsetAsync(p_ideg, 0, (size_t)N * sizeof(int));
    cudaMemsetAsync(p_colsum, 0, D * sizeof(float));
    cudaMemsetAsync(p_colsq, 0, D * sizeof(float));

    k_degrees<<<(E + 255) / 256, 256>>>(src, dst, E);
    k_cnorm<<<(N + 255) / 256, 256>>>(N);

    {
        long long threads = (long long)E * 32;
        int blocks = (int)((threads + 255) / 256);
        k_aggregate<<<blocks, 256>>>((const float4*)x, src, dst, E);
    }

    {
        const int smemBytes = 49152 * (int)sizeof(unsigned);  // 192 KB
        cudaFuncSetAttribute(k_gemm_tf32, cudaFuncAttributeMaxDynamicSharedMemorySize, smemBytes);
        int numTiles = (N + BM - 1) / BM;
        int grid = numTiles < 152 ? numTiles : 152;
        k_gemm_tf32<<<grid, 256, smemBytes>>>(
            (const float4*)x, W, b, Wr, br, N, numTiles);
    }

    k_bnparams<<<1, D>>>(gamma, beta, 1.0f / (float)N);
    {
        int total4 = N * (D / 4);
        k_bnapply<<<(total4 + 255) / 256, 256>>>((float4*)d_out, total4);
    }
}